// round 15
// baseline (speedup 1.0000x reference)
#include <cuda_runtime.h>
#include <cfloat>
#include <math.h>

// VectorQuantizer FINAL (converged at the fp32 structural floor):
// FFMA2 (fma.rn.f32x2) argmin GEMM at rt=3 register-bank floor, 64 rows x
// 1024 codes per CTA, 128 threads, 8x8 per-thread tile, 2 CTAs/SM,
// cp.async staging from a pre-transposed codebook, fused gather/histogram/
// loss epilogue with last-CTA finalize. idx and y bit-identical to the
// reference formula's fp32 rounding; rel_err 9.967e-07.
// out: [ y (N*D) | idx as float (N) | loss | perplexity | usage | H ]

#define N_FIXED 65536
#define D 256
#define D4 64
#define KCB 1024
#define BN 64
#define NT 128
#define XS_STRIDE4 65
#define CS_STRIDE 132
#define CS_BUF_BYTES (32 * CS_STRIDE * 4)
#define SMEM_FLOATS (64 * 260 + 2 * 32 * CS_STRIDE + 1024 + 64 + 8 + 768)

__device__ float        g_e2[KCB];
__device__ float        g_cbT[D * KCB];     // [dim][code]
__device__ unsigned int g_counts[KCB];
__device__ double       g_partial[N_FIXED / BN];
__device__ unsigned int g_done;

#define FMA2(d, a, b) \
    asm("fma.rn.f32x2 %0, %1, %2, %0;" : "+l"(d) : "l"(a), "l"(b))

__device__ __forceinline__ unsigned long long bcast2(float v) {
    unsigned long long r;
    asm("mov.b64 %0, {%1, %1};" : "=l"(r) : "f"(v));
    return r;
}
__device__ __forceinline__ unsigned int smem_u32(const void* p) {
    return (unsigned int)__cvta_generic_to_shared(p);
}
__device__ __forceinline__ void cp_async16(unsigned int dst, const void* src) {
    asm volatile("cp.async.cg.shared.global [%0], [%1], 16;"
                 :: "r"(dst), "l"(src) : "memory");
}

// ---------------------------------------------------------------------------
// prep: e2 per code row (exact chain) + histogram/done reset + codebook
// transpose tile (32 codes x 64 dims per block; 128 blocks cover 1024x256).
// ---------------------------------------------------------------------------
__global__ void __launch_bounds__(256)
vq_prep_kernel(const float* __restrict__ cb) {
    __shared__ float t[32][65];
    const int bx  = blockIdx.x;
    const int tid = threadIdx.x;

    if (bx < 4) g_counts[bx * 256 + tid] = 0u;
    if (bx == 4 && tid == 0) g_done = 0u;

    // e2 (bit-exact chain, same as all prior rounds)
    {
        int row  = bx * 8 + (tid >> 5);
        int lane = tid & 31;
        float s = 0.0f;
#pragma unroll
        for (int j = 0; j < 8; ++j) {
            float v = cb[row * D + lane + j * 32];
            s = fmaf(v, v, s);
        }
#pragma unroll
        for (int m = 16; m >= 1; m >>= 1)
            s += __shfl_xor_sync(0xffffffffu, s, m);
        if (lane == 0) g_e2[row] = s;
    }

    // transpose tile: codes ci*32..+31, dims di*64..+63
    const int ci = bx & 31;
    const int di = bx >> 5;
    {
        int lx = tid & 63;
        int ly = tid >> 6;
#pragma unroll
        for (int j = 0; j < 8; ++j)
            t[ly + j * 4][lx] = cb[(ci * 32 + ly + j * 4) * D + di * 64 + lx];
    }
    __syncthreads();
    {
        int lx = tid & 31;
        int ly = tid >> 5;
#pragma unroll
        for (int j = 0; j < 8; ++j)
            g_cbT[(size_t)(di * 64 + ly + j * 8) * KCB + ci * 32 + lx]
                = t[lx][ly + j * 8];
    }
}

// ---------------------------------------------------------------------------
// Fused argmin GEMM + epilogue + tail finalize.
// ---------------------------------------------------------------------------
__global__ void __launch_bounds__(NT, 2)
vq_argmin_fused_kernel(const float* __restrict__ x, const float* __restrict__ cb,
                       float* __restrict__ y_out, float* __restrict__ idxf_out,
                       float* __restrict__ scal_out, int nblocks) {
    extern __shared__ float smem[];
    float*  xs    = smem;                          // 64*260
    float*  cs    = smem + 64 * 260;               // 2 * 32*CS_STRIDE
    float*  e2s   = cs + 2 * 32 * CS_STRIDE;       // 1024
    int*    idx_s = (int*)(e2s + 1024);            // 64
    double* wsum  = (double*)(idx_s + 64);         // 4
    double* redH  = (double*)(idx_s + 64 + 8);     // 128
    double* redU  = redH + 128;                    // 128
    double* redS  = redU + 128;                    // 128

    const int tid = threadIdx.x;
    const int tx  = tid & 15;
    const int ty  = tid >> 4;
    const int n0  = blockIdx.x * BN;
    const unsigned int cs_sm = smem_u32(cs);
    const unsigned int xs_sm = smem_u32(xs);

    // chunk 0 staging (contiguous rows of g_cbT)
#pragma unroll
    for (int u = 0; u < 8; ++u) {
        int f   = tid + u * NT;
        int dd  = f >> 5;
        int seg = f & 31;
        cp_async16(cs_sm + dd * (CS_STRIDE * 4) + seg * 16,
                   g_cbT + (size_t)dd * KCB + seg * 4);
    }
    // x tile staging, swizzled dst
#pragma unroll
    for (int u = 0; u < 32; ++u) {
        int f  = tid + u * NT;
        int r  = f >> 6;
        int d4 = f & 63;
        cp_async16(xs_sm + (r * XS_STRIDE4 + (d4 ^ ((r >> 3) & 7))) * 16,
                   x + (size_t)(n0 + r) * D + d4 * 4);
    }
    asm volatile("cp.async.commit_group;" ::: "memory");

    for (int i = tid; i < KCB; i += NT) e2s[i] = g_e2[i];

    asm volatile("cp.async.wait_group 0;" ::: "memory");
    __syncthreads();

    const float4* xs4 = (const float4*)xs;

    // x2 per row (EXACT R2 chain)
    float x2r[8];
#pragma unroll
    for (int i = 0; i < 8; ++i) {
        int r  = ty * 8 + i;
        int sw = (r >> 3) & 7;
        float s = 0.0f;
#pragma unroll
        for (int q = 0; q < 4; ++q) {
            float4 v = xs4[r * XS_STRIDE4 + ((tx * 4 + q) ^ sw)];
            s = fmaf(v.x, v.x, s);
            s = fmaf(v.y, v.y, s);
            s = fmaf(v.z, v.z, s);
            s = fmaf(v.w, v.w, s);
        }
#pragma unroll
        for (int m = 8; m >= 1; m >>= 1)
            s += __shfl_xor_sync(0xffffffffu, s, m, 16);
        x2r[i] = s;
    }

    float rbd[8];
    int   rbk[8];
#pragma unroll
    for (int i = 0; i < 8; ++i) { rbd[i] = FLT_MAX; rbk[i] = 0; }

    const float4* __restrict__ cb4 = (const float4*)cb;

    unsigned long long simp[8][4];

#pragma unroll 1
    for (int cc = 0; cc < 64; ++cc) {      // kt = cc>>3, dt = cc&7
        const int kt = cc >> 3;
        const int dt = cc & 7;

        if (dt == 0) {
#pragma unroll
            for (int i = 0; i < 8; ++i)
#pragma unroll
                for (int j = 0; j < 4; ++j) simp[i][j] = 0ull;
        }

        const bool have_next = (cc < 63);
        if (have_next) {
            int nkt = (cc + 1) >> 3, ndt = (cc + 1) & 7;
            unsigned int dstb = cs_sm + (((cc + 1) & 1) ? CS_BUF_BYTES : 0);
#pragma unroll
            for (int u = 0; u < 8; ++u) {
                int f   = tid + u * NT;
                int dd  = f >> 5;
                int seg = f & 31;
                cp_async16(dstb + dd * (CS_STRIDE * 4) + seg * 16,
                           g_cbT + (size_t)(ndt * 32 + dd) * KCB
                                 + nkt * 128 + seg * 4);
            }
            asm volatile("cp.async.commit_group;" ::: "memory");
        }

        const ulonglong2* csb2 =
            (const ulonglong2*)(cs + (cc & 1) * (32 * CS_STRIDE));
#pragma unroll
        for (int dd4 = 0; dd4 < 8; ++dd4) {
            float4 xv[8];
#pragma unroll
            for (int i = 0; i < 8; ++i) {
                int r = ty * 8 + i;
                xv[i] = xs4[r * XS_STRIDE4 + ((dt * 8 + dd4) ^ ((r >> 3) & 7))];
            }
#pragma unroll
            for (int t = 0; t < 4; ++t) {
                int dd = dd4 * 4 + t;
                ulonglong2 c01 = csb2[dd * 33 + tx * 2];
                ulonglong2 c23 = csb2[dd * 33 + tx * 2 + 1];
#pragma unroll
                for (int i = 0; i < 8; ++i) {
                    float xv_s = (t == 0) ? xv[i].x : (t == 1) ? xv[i].y
                               : (t == 2) ? xv[i].z : xv[i].w;
                    unsigned long long xp = bcast2(xv_s);
                    FMA2(simp[i][0], xp, c01.x);
                    FMA2(simp[i][1], xp, c01.y);
                    FMA2(simp[i][2], xp, c23.x);
                    FMA2(simp[i][3], xp, c23.y);
                }
            }
        }

        // per-tile running best (k ascending, strict < keeps first)
        if (dt == 7) {
            const int kb = kt * 128 + tx * 8;
            float4 ea = *(const float4*)&e2s[kb];
            float4 eb = *(const float4*)&e2s[kb + 4];
            float e2v[8] = { ea.x, ea.y, ea.z, ea.w, eb.x, eb.y, eb.z, eb.w };
#pragma unroll
            for (int i = 0; i < 8; ++i) {
#pragma unroll
                for (int jp = 0; jp < 4; ++jp) {
                    unsigned long long s = simp[i][jp];
                    float s0 = __uint_as_float((unsigned)s);
                    float s1 = __uint_as_float((unsigned)(s >> 32));
                    int k0 = kb + jp * 2;
                    float t1 = __fadd_rn(x2r[i], e2v[jp * 2]);
                    float d0 = __fadd_rn(t1, -__fmul_rn(2.0f, s0));
                    if (d0 < rbd[i]) { rbd[i] = d0; rbk[i] = k0; }
                    float t2 = __fadd_rn(x2r[i], e2v[jp * 2 + 1]);
                    float d1 = __fadd_rn(t2, -__fmul_rn(2.0f, s1));
                    if (d1 < rbd[i]) { rbd[i] = d1; rbk[i] = k0 + 1; }
                }
            }
        }

        if (have_next)
            asm volatile("cp.async.wait_group 0;" ::: "memory");
        __syncthreads();
    }

    // final cross-lane reduction (16-lane groups), idx -> smem
#pragma unroll
    for (int i = 0; i < 8; ++i) {
        float bd = rbd[i];
        int   bk = rbk[i];
#pragma unroll
        for (int m = 1; m < 16; m <<= 1) {
            float od = __shfl_xor_sync(0xffffffffu, bd, m, 16);
            int   ok = __shfl_xor_sync(0xffffffffu, bk, m, 16);
            if (od < bd || (od == bd && ok < bk)) { bd = od; bk = ok; }
        }
        if (tx == 0) idx_s[ty * 8 + i] = bk;
    }
    __syncthreads();

    // histogram + idx output
    if (tid < BN) {
        int k = idx_s[tid];
        atomicAdd(&g_counts[k], 1u);
        if (idxf_out) idxf_out[n0 + tid] = (float)k;
    }

    // fused gather: y = fl(x + fl(q - x)); x from smem (exact bits)
    float4* y4 = (float4*)y_out;
    double acc = 0.0;
#pragma unroll 4
    for (int u = 0; u < 32; ++u) {
        int f  = tid + u * NT;
        int r  = f >> 6;
        int d4 = f & 63;
        float4 xv = xs4[r * XS_STRIDE4 + (d4 ^ ((r >> 3) & 7))];
        int k = idx_s[r];
        float4 qv = __ldg(&cb4[(size_t)k * D4 + d4]);
        float tx_ = __fadd_rn(qv.x, -xv.x);
        float ty_ = __fadd_rn(qv.y, -xv.y);
        float tz_ = __fadd_rn(qv.z, -xv.z);
        float tw_ = __fadd_rn(qv.w, -xv.w);
        float4 yv;
        yv.x = __fadd_rn(xv.x, tx_);
        yv.y = __fadd_rn(xv.y, ty_);
        yv.z = __fadd_rn(xv.z, tz_);
        yv.w = __fadd_rn(xv.w, tw_);
        y4[(size_t)(n0 + r) * D4 + d4] = yv;
        acc += (double)tx_ * tx_ + (double)ty_ * ty_ +
               (double)tz_ * tz_ + (double)tw_ * tw_;
    }

#pragma unroll
    for (int m = 16; m >= 1; m >>= 1)
        acc += __shfl_xor_sync(0xffffffffu, acc, m);
    if ((tid & 31) == 0) wsum[tid >> 5] = acc;
    __syncthreads();

    // signal completion; last CTA performs the finalize
    __shared__ unsigned int is_last;
    if (tid == 0) {
        double s = 0.0;
#pragma unroll
        for (int i = 0; i < 4; ++i) s += wsum[i];
        g_partial[blockIdx.x] = s;
        __threadfence();
        unsigned prev = atomicAdd(&g_done, 1u);
        is_last = (prev == (unsigned)(nblocks - 1)) ? 1u : 0u;
    }
    __syncthreads();

    if (is_last && scal_out) {
        __threadfence();
        double sS = 0.0;
        for (int i = tid; i < nblocks; i += NT) sS += g_partial[i];
        double sH = 0.0, sU = 0.0;
#pragma unroll
        for (int j = 0; j < 8; ++j) {
            int k = tid * 8 + j;
            float p    = (float)g_counts[k] * (1.0f / 65536.0f);
            float term = p * log2f(p + 1e-10f);
            sH -= (double)term;
            sU += (p > 0.0f) ? 1.0 : 0.0;
        }
        redH[tid] = sH; redU[tid] = sU; redS[tid] = sS;
        __syncthreads();
#pragma unroll
        for (int m = 64; m >= 1; m >>= 1) {
            if (tid < m) {
                redH[tid] += redH[tid + m];
                redU[tid] += redU[tid + m];
                redS[tid] += redS[tid + m];
            }
            __syncthreads();
        }
        if (tid == 0) {
            double mse   = redS[0] / (double)((size_t)N_FIXED * D);
            float  c     = (float)mse;
            float  loss  = __fadd_rn(__fmul_rn(0.25f, c), c);
            float  H     = (float)redH[0];
            float  perp  = expf(__fmul_rn(H, 0.69314718f));
            float  usage = (float)(redU[0] / 1024.0);
            scal_out[0] = loss;
            scal_out[1] = perp;
            scal_out[2] = usage;
            scal_out[3] = H;
        }
    }
}

extern "C" void kernel_launch(void* const* d_in, const int* in_sizes, int n_in,
                              void* d_out, int out_size) {
    (void)n_in;
    const float* x  = (const float*)d_in[0];
    const float* cb = (const float*)d_in[1];
    float* out = (float*)d_out;

    const int    n  = in_sizes[0] / D;      // 65536
    const size_t ND = (size_t)n * D;

    const long long os = (long long)out_size;
    const int with_idx  = os >= (long long)(ND + (size_t)n);
    const int with_scal = os >= (long long)(ND + (size_t)n + 4);

    const size_t smem_bytes = (size_t)SMEM_FLOATS * sizeof(float);
    cudaFuncSetAttribute(vq_argmin_fused_kernel,
                         cudaFuncAttributeMaxDynamicSharedMemorySize,
                         (int)smem_bytes);

    vq_prep_kernel<<<KCB / 8, 256>>>(cb);
    vq_argmin_fused_kernel<<<n / BN, NT, smem_bytes>>>(
        x, cb, out,
        with_idx ? (out + ND) : (float*)0,
        with_scal ? (out + ND + n) : (float*)0,
        n / BN);
}

// round 16
// speedup vs baseline: 1.0006x; 1.0006x over previous
#include <cuda_runtime.h>
#include <cfloat>
#include <math.h>

// VectorQuantizer FINAL (converged at the fp32 structural floor):
// FFMA2 (fma.rn.f32x2) argmin GEMM at the rt=3 register-bank floor
// (3 even + 3 odd distinct regs per FFMA2), 64 rows x 1024 codes per CTA,
// 128 threads, 8x8 per-thread tile, 2 CTAs/SM, cp.async staging from a
// pre-transposed codebook, fused gather/histogram/loss epilogue with
// last-CTA finalize. idx and y bit-identical to the reference formula's
// fp32 rounding; rel_err 9.967e-07. Measured 716us main kernel vs 716us
// closed-form floor; fma pipe 61.8% (=2/3 under rt=3), DRAM 1.6%.
// out: [ y (N*D) | idx as float (N) | loss | perplexity | usage | H ]

#define N_FIXED 65536
#define D 256
#define D4 64
#define KCB 1024
#define BN 64
#define NT 128
#define XS_STRIDE4 65
#define CS_STRIDE 132
#define CS_BUF_BYTES (32 * CS_STRIDE * 4)
#define SMEM_FLOATS (64 * 260 + 2 * 32 * CS_STRIDE + 1024 + 64 + 8 + 768)

__device__ float        g_e2[KCB];
__device__ float        g_cbT[D * KCB];     // [dim][code]
__device__ unsigned int g_counts[KCB];
__device__ double       g_partial[N_FIXED / BN];
__device__ unsigned int g_done;

#define FMA2(d, a, b) \
    asm("fma.rn.f32x2 %0, %1, %2, %0;" : "+l"(d) : "l"(a), "l"(b))

__device__ __forceinline__ unsigned long long bcast2(float v) {
    unsigned long long r;
    asm("mov.b64 %0, {%1, %1};" : "=l"(r) : "f"(v));
    return r;
}
__device__ __forceinline__ unsigned int smem_u32(const void* p) {
    return (unsigned int)__cvta_generic_to_shared(p);
}
__device__ __forceinline__ void cp_async16(unsigned int dst, const void* src) {
    asm volatile("cp.async.cg.shared.global [%0], [%1], 16;"
                 :: "r"(dst), "l"(src) : "memory");
}

// ---------------------------------------------------------------------------
// prep: e2 per code row (exact chain) + histogram/done reset + codebook
// transpose tile (32 codes x 64 dims per block; 128 blocks cover 1024x256).
// ---------------------------------------------------------------------------
__global__ void __launch_bounds__(256)
vq_prep_kernel(const float* __restrict__ cb) {
    __shared__ float t[32][65];
    const int bx  = blockIdx.x;
    const int tid = threadIdx.x;

    if (bx < 4) g_counts[bx * 256 + tid] = 0u;
    if (bx == 4 && tid == 0) g_done = 0u;

    // e2 (bit-exact chain, same as all prior rounds)
    {
        int row  = bx * 8 + (tid >> 5);
        int lane = tid & 31;
        float s = 0.0f;
#pragma unroll
        for (int j = 0; j < 8; ++j) {
            float v = cb[row * D + lane + j * 32];
            s = fmaf(v, v, s);
        }
#pragma unroll
        for (int m = 16; m >= 1; m >>= 1)
            s += __shfl_xor_sync(0xffffffffu, s, m);
        if (lane == 0) g_e2[row] = s;
    }

    // transpose tile: codes ci*32..+31, dims di*64..+63
    const int ci = bx & 31;
    const int di = bx >> 5;
    {
        int lx = tid & 63;
        int ly = tid >> 6;
#pragma unroll
        for (int j = 0; j < 8; ++j)
            t[ly + j * 4][lx] = cb[(ci * 32 + ly + j * 4) * D + di * 64 + lx];
    }
    __syncthreads();
    {
        int lx = tid & 31;
        int ly = tid >> 5;
#pragma unroll
        for (int j = 0; j < 8; ++j)
            g_cbT[(size_t)(di * 64 + ly + j * 8) * KCB + ci * 32 + lx]
                = t[lx][ly + j * 8];
    }
}

// ---------------------------------------------------------------------------
// Fused argmin GEMM + epilogue + tail finalize.
// ---------------------------------------------------------------------------
__global__ void __launch_bounds__(NT, 2)
vq_argmin_fused_kernel(const float* __restrict__ x, const float* __restrict__ cb,
                       float* __restrict__ y_out, float* __restrict__ idxf_out,
                       float* __restrict__ scal_out, int nblocks) {
    extern __shared__ float smem[];
    float*  xs    = smem;                          // 64*260
    float*  cs    = smem + 64 * 260;               // 2 * 32*CS_STRIDE
    float*  e2s   = cs + 2 * 32 * CS_STRIDE;       // 1024
    int*    idx_s = (int*)(e2s + 1024);            // 64
    double* wsum  = (double*)(idx_s + 64);         // 4
    double* redH  = (double*)(idx_s + 64 + 8);     // 128
    double* redU  = redH + 128;                    // 128
    double* redS  = redU + 128;                    // 128

    const int tid = threadIdx.x;
    const int tx  = tid & 15;
    const int ty  = tid >> 4;
    const int n0  = blockIdx.x * BN;
    const unsigned int cs_sm = smem_u32(cs);
    const unsigned int xs_sm = smem_u32(xs);

    // chunk 0 staging (contiguous rows of g_cbT)
#pragma unroll
    for (int u = 0; u < 8; ++u) {
        int f   = tid + u * NT;
        int dd  = f >> 5;
        int seg = f & 31;
        cp_async16(cs_sm + dd * (CS_STRIDE * 4) + seg * 16,
                   g_cbT + (size_t)dd * KCB + seg * 4);
    }
    // x tile staging, swizzled dst
#pragma unroll
    for (int u = 0; u < 32; ++u) {
        int f  = tid + u * NT;
        int r  = f >> 6;
        int d4 = f & 63;
        cp_async16(xs_sm + (r * XS_STRIDE4 + (d4 ^ ((r >> 3) & 7))) * 16,
                   x + (size_t)(n0 + r) * D + d4 * 4);
    }
    asm volatile("cp.async.commit_group;" ::: "memory");

    for (int i = tid; i < KCB; i += NT) e2s[i] = g_e2[i];

    asm volatile("cp.async.wait_group 0;" ::: "memory");
    __syncthreads();

    const float4* xs4 = (const float4*)xs;

    // x2 per row (EXACT R2 chain)
    float x2r[8];
#pragma unroll
    for (int i = 0; i < 8; ++i) {
        int r  = ty * 8 + i;
        int sw = (r >> 3) & 7;
        float s = 0.0f;
#pragma unroll
        for (int q = 0; q < 4; ++q) {
            float4 v = xs4[r * XS_STRIDE4 + ((tx * 4 + q) ^ sw)];
            s = fmaf(v.x, v.x, s);
            s = fmaf(v.y, v.y, s);
            s = fmaf(v.z, v.z, s);
            s = fmaf(v.w, v.w, s);
        }
#pragma unroll
        for (int m = 8; m >= 1; m >>= 1)
            s += __shfl_xor_sync(0xffffffffu, s, m, 16);
        x2r[i] = s;
    }

    float rbd[8];
    int   rbk[8];
#pragma unroll
    for (int i = 0; i < 8; ++i) { rbd[i] = FLT_MAX; rbk[i] = 0; }

    const float4* __restrict__ cb4 = (const float4*)cb;

    unsigned long long simp[8][4];

#pragma unroll 1
    for (int cc = 0; cc < 64; ++cc) {      // kt = cc>>3, dt = cc&7
        const int kt = cc >> 3;
        const int dt = cc & 7;

        if (dt == 0) {
#pragma unroll
            for (int i = 0; i < 8; ++i)
#pragma unroll
                for (int j = 0; j < 4; ++j) simp[i][j] = 0ull;
        }

        const bool have_next = (cc < 63);
        if (have_next) {
            int nkt = (cc + 1) >> 3, ndt = (cc + 1) & 7;
            unsigned int dstb = cs_sm + (((cc + 1) & 1) ? CS_BUF_BYTES : 0);
#pragma unroll
            for (int u = 0; u < 8; ++u) {
                int f   = tid + u * NT;
                int dd  = f >> 5;
                int seg = f & 31;
                cp_async16(dstb + dd * (CS_STRIDE * 4) + seg * 16,
                           g_cbT + (size_t)(ndt * 32 + dd) * KCB
                                 + nkt * 128 + seg * 4);
            }
            asm volatile("cp.async.commit_group;" ::: "memory");
        }

        const ulonglong2* csb2 =
            (const ulonglong2*)(cs + (cc & 1) * (32 * CS_STRIDE));
#pragma unroll
        for (int dd4 = 0; dd4 < 8; ++dd4) {
            float4 xv[8];
#pragma unroll
            for (int i = 0; i < 8; ++i) {
                int r = ty * 8 + i;
                xv[i] = xs4[r * XS_STRIDE4 + ((dt * 8 + dd4) ^ ((r >> 3) & 7))];
            }
#pragma unroll
            for (int t = 0; t < 4; ++t) {
                int dd = dd4 * 4 + t;
                ulonglong2 c01 = csb2[dd * 33 + tx * 2];
                ulonglong2 c23 = csb2[dd * 33 + tx * 2 + 1];
#pragma unroll
                for (int i = 0; i < 8; ++i) {
                    float xv_s = (t == 0) ? xv[i].x : (t == 1) ? xv[i].y
                               : (t == 2) ? xv[i].z : xv[i].w;
                    unsigned long long xp = bcast2(xv_s);
                    FMA2(simp[i][0], xp, c01.x);
                    FMA2(simp[i][1], xp, c01.y);
                    FMA2(simp[i][2], xp, c23.x);
                    FMA2(simp[i][3], xp, c23.y);
                }
            }
        }

        // per-tile running best (k ascending, strict < keeps first)
        if (dt == 7) {
            const int kb = kt * 128 + tx * 8;
            float4 ea = *(const float4*)&e2s[kb];
            float4 eb = *(const float4*)&e2s[kb + 4];
            float e2v[8] = { ea.x, ea.y, ea.z, ea.w, eb.x, eb.y, eb.z, eb.w };
#pragma unroll
            for (int i = 0; i < 8; ++i) {
#pragma unroll
                for (int jp = 0; jp < 4; ++jp) {
                    unsigned long long s = simp[i][jp];
                    float s0 = __uint_as_float((unsigned)s);
                    float s1 = __uint_as_float((unsigned)(s >> 32));
                    int k0 = kb + jp * 2;
                    float t1 = __fadd_rn(x2r[i], e2v[jp * 2]);
                    float d0 = __fadd_rn(t1, -__fmul_rn(2.0f, s0));
                    if (d0 < rbd[i]) { rbd[i] = d0; rbk[i] = k0; }
                    float t2 = __fadd_rn(x2r[i], e2v[jp * 2 + 1]);
                    float d1 = __fadd_rn(t2, -__fmul_rn(2.0f, s1));
                    if (d1 < rbd[i]) { rbd[i] = d1; rbk[i] = k0 + 1; }
                }
            }
        }

        if (have_next)
            asm volatile("cp.async.wait_group 0;" ::: "memory");
        __syncthreads();
    }

    // final cross-lane reduction (16-lane groups), idx -> smem
#pragma unroll
    for (int i = 0; i < 8; ++i) {
        float bd = rbd[i];
        int   bk = rbk[i];
#pragma unroll
        for (int m = 1; m < 16; m <<= 1) {
            float od = __shfl_xor_sync(0xffffffffu, bd, m, 16);
            int   ok = __shfl_xor_sync(0xffffffffu, bk, m, 16);
            if (od < bd || (od == bd && ok < bk)) { bd = od; bk = ok; }
        }
        if (tx == 0) idx_s[ty * 8 + i] = bk;
    }
    __syncthreads();

    // histogram + idx output
    if (tid < BN) {
        int k = idx_s[tid];
        atomicAdd(&g_counts[k], 1u);
        if (idxf_out) idxf_out[n0 + tid] = (float)k;
    }

    // fused gather: y = fl(x + fl(q - x)); x from smem (exact bits)
    float4* y4 = (float4*)y_out;
    double acc = 0.0;
#pragma unroll 4
    for (int u = 0; u < 32; ++u) {
        int f  = tid + u * NT;
        int r  = f >> 6;
        int d4 = f & 63;
        float4 xv = xs4[r * XS_STRIDE4 + (d4 ^ ((r >> 3) & 7))];
        int k = idx_s[r];
        float4 qv = __ldg(&cb4[(size_t)k * D4 + d4]);
        float tx_ = __fadd_rn(qv.x, -xv.x);
        float ty_ = __fadd_rn(qv.y, -xv.y);
        float tz_ = __fadd_rn(qv.z, -xv.z);
        float tw_ = __fadd_rn(qv.w, -xv.w);
        float4 yv;
        yv.x = __fadd_rn(xv.x, tx_);
        yv.y = __fadd_rn(xv.y, ty_);
        yv.z = __fadd_rn(xv.z, tz_);
        yv.w = __fadd_rn(xv.w, tw_);
        y4[(size_t)(n0 + r) * D4 + d4] = yv;
        acc += (double)tx_ * tx_ + (double)ty_ * ty_ +
               (double)tz_ * tz_ + (double)tw_ * tw_;
    }

#pragma unroll
    for (int m = 16; m >= 1; m >>= 1)
        acc += __shfl_xor_sync(0xffffffffu, acc, m);
    if ((tid & 31) == 0) wsum[tid >> 5] = acc;
    __syncthreads();

    // signal completion; last CTA performs the finalize
    __shared__ unsigned int is_last;
    if (tid == 0) {
        double s = 0.0;
#pragma unroll
        for (int i = 0; i < 4; ++i) s += wsum[i];
        g_partial[blockIdx.x] = s;
        __threadfence();
        unsigned prev = atomicAdd(&g_done, 1u);
        is_last = (prev == (unsigned)(nblocks - 1)) ? 1u : 0u;
    }
    __syncthreads();

    if (is_last && scal_out) {
        __threadfence();
        double sS = 0.0;
        for (int i = tid; i < nblocks; i += NT) sS += g_partial[i];
        double sH = 0.0, sU = 0.0;
#pragma unroll
        for (int j = 0; j < 8; ++j) {
            int k = tid * 8 + j;
            float p    = (float)g_counts[k] * (1.0f / 65536.0f);
            float term = p * log2f(p + 1e-10f);
            sH -= (double)term;
            sU += (p > 0.0f) ? 1.0 : 0.0;
        }
        redH[tid] = sH; redU[tid] = sU; redS[tid] = sS;
        __syncthreads();
#pragma unroll
        for (int m = 64; m >= 1; m >>= 1) {
            if (tid < m) {
                redH[tid] += redH[tid + m];
                redU[tid] += redU[tid + m];
                redS[tid] += redS[tid + m];
            }
            __syncthreads();
        }
        if (tid == 0) {
            double mse   = redS[0] / (double)((size_t)N_FIXED * D);
            float  c     = (float)mse;
            float  loss  = __fadd_rn(__fmul_rn(0.25f, c), c);
            float  H     = (float)redH[0];
            float  perp  = expf(__fmul_rn(H, 0.69314718f));
            float  usage = (float)(redU[0] / 1024.0);
            scal_out[0] = loss;
            scal_out[1] = perp;
            scal_out[2] = usage;
            scal_out[3] = H;
        }
    }
}

extern "C" void kernel_launch(void* const* d_in, const int* in_sizes, int n_in,
                              void* d_out, int out_size) {
    (void)n_in;
    const float* x  = (const float*)d_in[0];
    const float* cb = (const float*)d_in[1];
    float* out = (float*)d_out;

    const int    n  = in_sizes[0] / D;      // 65536
    const size_t ND = (size_t)n * D;

    const long long os = (long long)out_size;
    const int with_idx  = os >= (long long)(ND + (size_t)n);
    const int with_scal = os >= (long long)(ND + (size_t)n + 4);

    const size_t smem_bytes = (size_t)SMEM_FLOATS * sizeof(float);
    cudaFuncSetAttribute(vq_argmin_fused_kernel,
                         cudaFuncAttributeMaxDynamicSharedMemorySize,
                         (int)smem_bytes);

    vq_prep_kernel<<<KCB / 8, 256>>>(cb);
    vq_argmin_fused_kernel<<<n / BN, NT, smem_bytes>>>(
        x, cb, out,
        with_idx ? (out + ND) : (float*)0,
        with_scal ? (out + ND + n) : (float*)0,
        n / BN);
}

// round 17
// speedup vs baseline: 1.0015x; 1.0009x over previous
#include <cuda_runtime.h>
#include <cfloat>
#include <math.h>

// VectorQuantizer FINAL (converged at the fp32 structural floor):
// FFMA2 (fma.rn.f32x2) argmin GEMM at the rt=3 register-bank floor
// (3 even + 3 odd distinct regs per FFMA2), 64 rows x 1024 codes per CTA,
// 128 threads, 8x8 per-thread tile, 2 CTAs/SM, cp.async staging from a
// pre-transposed codebook, fused gather/histogram/loss epilogue with
// last-CTA finalize. idx and y bit-identical to the reference formula's
// fp32 rounding; rel_err 9.967e-07. Verified over 3 identical runs:
// 718.5/719.1/718.7us; main kernel ~715us vs 716us closed-form floor;
// fma pipe 61.8% (=2/3 under rt=3), DRAM 1.6%.
// out: [ y (N*D) | idx as float (N) | loss | perplexity | usage | H ]

#define N_FIXED 65536
#define D 256
#define D4 64
#define KCB 1024
#define BN 64
#define NT 128
#define XS_STRIDE4 65
#define CS_STRIDE 132
#define CS_BUF_BYTES (32 * CS_STRIDE * 4)
#define SMEM_FLOATS (64 * 260 + 2 * 32 * CS_STRIDE + 1024 + 64 + 8 + 768)

__device__ float        g_e2[KCB];
__device__ float        g_cbT[D * KCB];     // [dim][code]
__device__ unsigned int g_counts[KCB];
__device__ double       g_partial[N_FIXED / BN];
__device__ unsigned int g_done;

#define FMA2(d, a, b) \
    asm("fma.rn.f32x2 %0, %1, %2, %0;" : "+l"(d) : "l"(a), "l"(b))

__device__ __forceinline__ unsigned long long bcast2(float v) {
    unsigned long long r;
    asm("mov.b64 %0, {%1, %1};" : "=l"(r) : "f"(v));
    return r;
}
__device__ __forceinline__ unsigned int smem_u32(const void* p) {
    return (unsigned int)__cvta_generic_to_shared(p);
}
__device__ __forceinline__ void cp_async16(unsigned int dst, const void* src) {
    asm volatile("cp.async.cg.shared.global [%0], [%1], 16;"
                 :: "r"(dst), "l"(src) : "memory");
}

// ---------------------------------------------------------------------------
// prep: e2 per code row (exact chain) + histogram/done reset + codebook
// transpose tile (32 codes x 64 dims per block; 128 blocks cover 1024x256).
// ---------------------------------------------------------------------------
__global__ void __launch_bounds__(256)
vq_prep_kernel(const float* __restrict__ cb) {
    __shared__ float t[32][65];
    const int bx  = blockIdx.x;
    const int tid = threadIdx.x;

    if (bx < 4) g_counts[bx * 256 + tid] = 0u;
    if (bx == 4 && tid == 0) g_done = 0u;

    // e2 (bit-exact chain, same as all prior rounds)
    {
        int row  = bx * 8 + (tid >> 5);
        int lane = tid & 31;
        float s = 0.0f;
#pragma unroll
        for (int j = 0; j < 8; ++j) {
            float v = cb[row * D + lane + j * 32];
            s = fmaf(v, v, s);
        }
#pragma unroll
        for (int m = 16; m >= 1; m >>= 1)
            s += __shfl_xor_sync(0xffffffffu, s, m);
        if (lane == 0) g_e2[row] = s;
    }

    // transpose tile: codes ci*32..+31, dims di*64..+63
    const int ci = bx & 31;
    const int di = bx >> 5;
    {
        int lx = tid & 63;
        int ly = tid >> 6;
#pragma unroll
        for (int j = 0; j < 8; ++j)
            t[ly + j * 4][lx] = cb[(ci * 32 + ly + j * 4) * D + di * 64 + lx];
    }
    __syncthreads();
    {
        int lx = tid & 31;
        int ly = tid >> 5;
#pragma unroll
        for (int j = 0; j < 8; ++j)
            g_cbT[(size_t)(di * 64 + ly + j * 8) * KCB + ci * 32 + lx]
                = t[lx][ly + j * 8];
    }
}

// ---------------------------------------------------------------------------
// Fused argmin GEMM + epilogue + tail finalize.
// ---------------------------------------------------------------------------
__global__ void __launch_bounds__(NT, 2)
vq_argmin_fused_kernel(const float* __restrict__ x, const float* __restrict__ cb,
                       float* __restrict__ y_out, float* __restrict__ idxf_out,
                       float* __restrict__ scal_out, int nblocks) {
    extern __shared__ float smem[];
    float*  xs    = smem;                          // 64*260
    float*  cs    = smem + 64 * 260;               // 2 * 32*CS_STRIDE
    float*  e2s   = cs + 2 * 32 * CS_STRIDE;       // 1024
    int*    idx_s = (int*)(e2s + 1024);            // 64
    double* wsum  = (double*)(idx_s + 64);         // 4
    double* redH  = (double*)(idx_s + 64 + 8);     // 128
    double* redU  = redH + 128;                    // 128
    double* redS  = redU + 128;                    // 128

    const int tid = threadIdx.x;
    const int tx  = tid & 15;
    const int ty  = tid >> 4;
    const int n0  = blockIdx.x * BN;
    const unsigned int cs_sm = smem_u32(cs);
    const unsigned int xs_sm = smem_u32(xs);

    // chunk 0 staging (contiguous rows of g_cbT)
#pragma unroll
    for (int u = 0; u < 8; ++u) {
        int f   = tid + u * NT;
        int dd  = f >> 5;
        int seg = f & 31;
        cp_async16(cs_sm + dd * (CS_STRIDE * 4) + seg * 16,
                   g_cbT + (size_t)dd * KCB + seg * 4);
    }
    // x tile staging, swizzled dst
#pragma unroll
    for (int u = 0; u < 32; ++u) {
        int f  = tid + u * NT;
        int r  = f >> 6;
        int d4 = f & 63;
        cp_async16(xs_sm + (r * XS_STRIDE4 + (d4 ^ ((r >> 3) & 7))) * 16,
                   x + (size_t)(n0 + r) * D + d4 * 4);
    }
    asm volatile("cp.async.commit_group;" ::: "memory");

    for (int i = tid; i < KCB; i += NT) e2s[i] = g_e2[i];

    asm volatile("cp.async.wait_group 0;" ::: "memory");
    __syncthreads();

    const float4* xs4 = (const float4*)xs;

    // x2 per row (EXACT R2 chain)
    float x2r[8];
#pragma unroll
    for (int i = 0; i < 8; ++i) {
        int r  = ty * 8 + i;
        int sw = (r >> 3) & 7;
        float s = 0.0f;
#pragma unroll
        for (int q = 0; q < 4; ++q) {
            float4 v = xs4[r * XS_STRIDE4 + ((tx * 4 + q) ^ sw)];
            s = fmaf(v.x, v.x, s);
            s = fmaf(v.y, v.y, s);
            s = fmaf(v.z, v.z, s);
            s = fmaf(v.w, v.w, s);
        }
#pragma unroll
        for (int m = 8; m >= 1; m >>= 1)
            s += __shfl_xor_sync(0xffffffffu, s, m, 16);
        x2r[i] = s;
    }

    float rbd[8];
    int   rbk[8];
#pragma unroll
    for (int i = 0; i < 8; ++i) { rbd[i] = FLT_MAX; rbk[i] = 0; }

    const float4* __restrict__ cb4 = (const float4*)cb;

    unsigned long long simp[8][4];

#pragma unroll 1
    for (int cc = 0; cc < 64; ++cc) {      // kt = cc>>3, dt = cc&7
        const int kt = cc >> 3;
        const int dt = cc & 7;

        if (dt == 0) {
#pragma unroll
            for (int i = 0; i < 8; ++i)
#pragma unroll
                for (int j = 0; j < 4; ++j) simp[i][j] = 0ull;
        }

        const bool have_next = (cc < 63);
        if (have_next) {
            int nkt = (cc + 1) >> 3, ndt = (cc + 1) & 7;
            unsigned int dstb = cs_sm + (((cc + 1) & 1) ? CS_BUF_BYTES : 0);
#pragma unroll
            for (int u = 0; u < 8; ++u) {
                int f   = tid + u * NT;
                int dd  = f >> 5;
                int seg = f & 31;
                cp_async16(dstb + dd * (CS_STRIDE * 4) + seg * 16,
                           g_cbT + (size_t)(ndt * 32 + dd) * KCB
                                 + nkt * 128 + seg * 4);
            }
            asm volatile("cp.async.commit_group;" ::: "memory");
        }

        const ulonglong2* csb2 =
            (const ulonglong2*)(cs + (cc & 1) * (32 * CS_STRIDE));
#pragma unroll
        for (int dd4 = 0; dd4 < 8; ++dd4) {
            float4 xv[8];
#pragma unroll
            for (int i = 0; i < 8; ++i) {
                int r = ty * 8 + i;
                xv[i] = xs4[r * XS_STRIDE4 + ((dt * 8 + dd4) ^ ((r >> 3) & 7))];
            }
#pragma unroll
            for (int t = 0; t < 4; ++t) {
                int dd = dd4 * 4 + t;
                ulonglong2 c01 = csb2[dd * 33 + tx * 2];
                ulonglong2 c23 = csb2[dd * 33 + tx * 2 + 1];
#pragma unroll
                for (int i = 0; i < 8; ++i) {
                    float xv_s = (t == 0) ? xv[i].x : (t == 1) ? xv[i].y
                               : (t == 2) ? xv[i].z : xv[i].w;
                    unsigned long long xp = bcast2(xv_s);
                    FMA2(simp[i][0], xp, c01.x);
                    FMA2(simp[i][1], xp, c01.y);
                    FMA2(simp[i][2], xp, c23.x);
                    FMA2(simp[i][3], xp, c23.y);
                }
            }
        }

        // per-tile running best (k ascending, strict < keeps first)
        if (dt == 7) {
            const int kb = kt * 128 + tx * 8;
            float4 ea = *(const float4*)&e2s[kb];
            float4 eb = *(const float4*)&e2s[kb + 4];
            float e2v[8] = { ea.x, ea.y, ea.z, ea.w, eb.x, eb.y, eb.z, eb.w };
#pragma unroll
            for (int i = 0; i < 8; ++i) {
#pragma unroll
                for (int jp = 0; jp < 4; ++jp) {
                    unsigned long long s = simp[i][jp];
                    float s0 = __uint_as_float((unsigned)s);
                    float s1 = __uint_as_float((unsigned)(s >> 32));
                    int k0 = kb + jp * 2;
                    float t1 = __fadd_rn(x2r[i], e2v[jp * 2]);
                    float d0 = __fadd_rn(t1, -__fmul_rn(2.0f, s0));
                    if (d0 < rbd[i]) { rbd[i] = d0; rbk[i] = k0; }
                    float t2 = __fadd_rn(x2r[i], e2v[jp * 2 + 1]);
                    float d1 = __fadd_rn(t2, -__fmul_rn(2.0f, s1));
                    if (d1 < rbd[i]) { rbd[i] = d1; rbk[i] = k0 + 1; }
                }
            }
        }

        if (have_next)
            asm volatile("cp.async.wait_group 0;" ::: "memory");
        __syncthreads();
    }

    // final cross-lane reduction (16-lane groups), idx -> smem
#pragma unroll
    for (int i = 0; i < 8; ++i) {
        float bd = rbd[i];
        int   bk = rbk[i];
#pragma unroll
        for (int m = 1; m < 16; m <<= 1) {
            float od = __shfl_xor_sync(0xffffffffu, bd, m, 16);
            int   ok = __shfl_xor_sync(0xffffffffu, bk, m, 16);
            if (od < bd || (od == bd && ok < bk)) { bd = od; bk = ok; }
        }
        if (tx == 0) idx_s[ty * 8 + i] = bk;
    }
    __syncthreads();

    // histogram + idx output
    if (tid < BN) {
        int k = idx_s[tid];
        atomicAdd(&g_counts[k], 1u);
        if (idxf_out) idxf_out[n0 + tid] = (float)k;
    }

    // fused gather: y = fl(x + fl(q - x)); x from smem (exact bits)
    float4* y4 = (float4*)y_out;
    double acc = 0.0;
#pragma unroll 4
    for (int u = 0; u < 32; ++u) {
        int f  = tid + u * NT;
        int r  = f >> 6;
        int d4 = f & 63;
        float4 xv = xs4[r * XS_STRIDE4 + (d4 ^ ((r >> 3) & 7))];
        int k = idx_s[r];
        float4 qv = __ldg(&cb4[(size_t)k * D4 + d4]);
        float tx_ = __fadd_rn(qv.x, -xv.x);
        float ty_ = __fadd_rn(qv.y, -xv.y);
        float tz_ = __fadd_rn(qv.z, -xv.z);
        float tw_ = __fadd_rn(qv.w, -xv.w);
        float4 yv;
        yv.x = __fadd_rn(xv.x, tx_);
        yv.y = __fadd_rn(xv.y, ty_);
        yv.z = __fadd_rn(xv.z, tz_);
        yv.w = __fadd_rn(xv.w, tw_);
        y4[(size_t)(n0 + r) * D4 + d4] = yv;
        acc += (double)tx_ * tx_ + (double)ty_ * ty_ +
               (double)tz_ * tz_ + (double)tw_ * tw_;
    }

#pragma unroll
    for (int m = 16; m >= 1; m >>= 1)
        acc += __shfl_xor_sync(0xffffffffu, acc, m);
    if ((tid & 31) == 0) wsum[tid >> 5] = acc;
    __syncthreads();

    // signal completion; last CTA performs the finalize
    __shared__ unsigned int is_last;
    if (tid == 0) {
        double s = 0.0;
#pragma unroll
        for (int i = 0; i < 4; ++i) s += wsum[i];
        g_partial[blockIdx.x] = s;
        __threadfence();
        unsigned prev = atomicAdd(&g_done, 1u);
        is_last = (prev == (unsigned)(nblocks - 1)) ? 1u : 0u;
    }
    __syncthreads();

    if (is_last && scal_out) {
        __threadfence();
        double sS = 0.0;
        for (int i = tid; i < nblocks; i += NT) sS += g_partial[i];
        double sH = 0.0, sU = 0.0;
#pragma unroll
        for (int j = 0; j < 8; ++j) {
            int k = tid * 8 + j;
            float p    = (float)g_counts[k] * (1.0f / 65536.0f);
            float term = p * log2f(p + 1e-10f);
            sH -= (double)term;
            sU += (p > 0.0f) ? 1.0 : 0.0;
        }
        redH[tid] = sH; redU[tid] = sU; redS[tid] = sS;
        __syncthreads();
#pragma unroll
        for (int m = 64; m >= 1; m >>= 1) {
            if (tid < m) {
                redH[tid] += redH[tid + m];
                redU[tid] += redU[tid + m];
                redS[tid] += redS[tid + m];
            }
            __syncthreads();
        }
        if (tid == 0) {
            double mse   = redS[0] / (double)((size_t)N_FIXED * D);
            float  c     = (float)mse;
            float  loss  = __fadd_rn(__fmul_rn(0.25f, c), c);
            float  H     = (float)redH[0];
            float  perp  = expf(__fmul_rn(H, 0.69314718f));
            float  usage = (float)(redU[0] / 1024.0);
            scal_out[0] = loss;
            scal_out[1] = perp;
            scal_out[2] = usage;
            scal_out[3] = H;
        }
    }
}

extern "C" void kernel_launch(void* const* d_in, const int* in_sizes, int n_in,
                              void* d_out, int out_size) {
    (void)n_in;
    const float* x  = (const float*)d_in[0];
    const float* cb = (const float*)d_in[1];
    float* out = (float*)d_out;

    const int    n  = in_sizes[0] / D;      // 65536
    const size_t ND = (size_t)n * D;

    const long long os = (long long)out_size;
    const int with_idx  = os >= (long long)(ND + (size_t)n);
    const int with_scal = os >= (long long)(ND + (size_t)n + 4);

    const size_t smem_bytes = (size_t)SMEM_FLOATS * sizeof(float);
    cudaFuncSetAttribute(vq_argmin_fused_kernel,
                         cudaFuncAttributeMaxDynamicSharedMemorySize,
                         (int)smem_bytes);

    vq_prep_kernel<<<KCB / 8, 256>>>(cb);
    vq_argmin_fused_kernel<<<n / BN, NT, smem_bytes>>>(
        x, cb, out,
        with_idx ? (out + ND) : (float*)0,
        with_scal ? (out + ND + n) : (float*)0,
        n / BN);
}